// round 6
// baseline (speedup 1.0000x reference)
#include <cuda_runtime.h>
#include <math.h>

#define C_CLASSES 10000
#define K_PROTO   4
#define D_DIM     2048
#define N_PROTO   (C_CLASSES * K_PROTO)     // 40000
#define WARPS_PER_BLOCK 8
#define BLOCK1 (WARPS_PER_BLOCK * 32)       // 256
#define N_TILES (N_PROTO / WARPS_PER_BLOCK) // 5000 tiles of 8 prototypes
#define GRID (148 * 6)                      // 888 persistent blocks

// scratch (no cudaMalloc allowed). g_pmin/g_psum/g_lbl fully overwritten each
// run; g_ticket reset by the last block -> graph-replay deterministic.
__device__ float g_pmin[GRID];
__device__ float g_psum[GRID];
__device__ float g_lbl[K_PROTO];
__device__ unsigned int g_ticket = 0;

__global__ __launch_bounds__(BLOCK1) void fused_kernel(
    const float* __restrict__ proto, const float* __restrict__ feat,
    const int* __restrict__ label, float* __restrict__ out) {
    __shared__ float4 sf[D_DIM / 4];        // 8 KB feature tile
    __shared__ float  sm[WARPS_PER_BLOCK], ss[WARPS_PER_BLOCK];
    __shared__ bool   amLast;

    const int tid  = threadIdx.x;
    const int lane = tid & 31;
    const int warp = tid >> 5;
    const int lbl  = *label;

    const float4* __restrict__ f4 = reinterpret_cast<const float4*>(feat);
    for (int i = tid; i < D_DIM / 4; i += BLOCK1) sf[i] = f4[i];
    __syncthreads();

    // ---- streaming phase: grid-stride over tiles; per-warp running (m, s) ----
    float m = INFINITY, s = 0.0f;
    for (int t = blockIdx.x; t < N_TILES; t += GRID) {
        const int p = t * WARPS_PER_BLOCK + warp;
        const float4* __restrict__ pp =
            reinterpret_cast<const float4*>(proto + (size_t)p * D_DIM);
        float acc = 0.0f;
#pragma unroll
        for (int i = 0; i < 16; ++i) {      // 16 float4 per lane = 2048/(32*4)
            float4 v = __ldcs(pp + lane + i * 32);  // read-once data
            float4 f = sf[lane + i * 32];
            float dx = v.x - f.x;
            float dy = v.y - f.y;
            float dz = v.z - f.z;
            float dw = v.w - f.w;
            acc += dx * dx + dy * dy + dz * dz + dw * dw;
        }
#pragma unroll
        for (int o = 16; o > 0; o >>= 1)    // full butterfly: all lanes get acc
            acc += __shfl_xor_sync(0xFFFFFFFFu, acc, o);

        if (lane == 0 && (p >> 2) == lbl) g_lbl[p & 3] = acc;

        // online logsumexp update (redundant across lanes, register-only)
        float nm = fminf(m, acc);
        s = s * __expf(nm - m) + __expf(nm - acc);
        m = nm;
    }

    // ---- block partial: merge 8 warp pairs ----
    if (lane == 0) { sm[warp] = m; ss[warp] = s; }
    __syncthreads();
    if (tid == 0) {
        float bm = sm[0], bs = ss[0];
#pragma unroll
        for (int w = 1; w < WARPS_PER_BLOCK; ++w) {
            float nm = fminf(bm, sm[w]);
            bs = bs * __expf(nm - bm) + ss[w] * __expf(nm - sm[w]);
            bm = nm;
        }
        g_pmin[blockIdx.x] = bm;
        g_psum[blockIdx.x] = bs;
        __threadfence();
        unsigned int tk = atomicAdd(&g_ticket, 1u);
        amLast = (tk == GRID - 1);
    }
    __syncthreads();
    if (!amLast) return;

    // ---- last block: merge GRID pairs (7 KB, L2-hot), fixed order ----
    __shared__ float rm[BLOCK1], rs[BLOCK1];
    float km = INFINITY, ks = 0.0f;
    for (int i = tid; i < GRID; i += BLOCK1) {
        float pm = g_pmin[i], ps = g_psum[i];
        float nm = fminf(km, pm);
        ks = ks * __expf(nm - km) + ps * __expf(nm - pm);
        km = nm;
    }
    rm[tid] = km; rs[tid] = ks;
    __syncthreads();
#pragma unroll
    for (int step = BLOCK1 / 2; step > 0; step >>= 1) {
        if (tid < step) {
            float m1 = rm[tid], s1 = rs[tid];
            float m2 = rm[tid + step], s2 = rs[tid + step];
            float nm = fminf(m1, m2);
            rm[tid] = nm;
            rs[tid] = s1 * __expf(nm - m1) + s2 * __expf(nm - m2);
        }
        __syncthreads();
    }

    if (tid == 0) {
        const float log_one = -rm[0] + logf(rs[0]);
        float prob = 0.0f;
#pragma unroll
        for (int k = 0; k < K_PROTO; ++k)
            prob += log_one + g_lbl[k];     // log_one - logits
        out[0] = prob;
        g_ticket = 0;                        // reset for next graph replay
        __threadfence();
    }
}

extern "C" void kernel_launch(void* const* d_in, const int* in_sizes, int n_in,
                              void* d_out, int out_size) {
    const float* feature = (const float*)d_in[0];
    const int*   label   = (const int*)d_in[1];
    const float* protos  = (const float*)d_in[2];
    float* out = (float*)d_out;

    fused_kernel<<<GRID, BLOCK1>>>(protos, feature, label, out);
}